// round 16
// baseline (speedup 1.0000x reference)
#include <cuda_runtime.h>
#include <cuda_bf16.h>
#include <cstdint>

#define HID   2048
#define KSEL  256
#define NTOK  16384
#define NTHR  256
#define FULLW 0xFFFFFFFFu
// Filter: v >= 0.875f  <=>  key >= 0xBF600000  <=>  bin >= 1531 (bin-aligned).
#define FTHR  0.875f
#define BASE  1531u          // first bin of the 64-bin window
#define NBINS 64u            // window [1531, 1595): covers values up to ~57344
#define SENT  0xFFFFFFFFu

__device__ int g_ids64;

// Detect int32 vs int64 ids (odd 32-bit words all zero => int64).
__global__ void detect_ids_kernel(const unsigned int* __restrict__ w) {
    __shared__ unsigned acc[NTHR];
    unsigned v = 0;
    for (int i = threadIdx.x; i < NTOK / 2; i += NTHR) v |= w[2 * i + 1];
    acc[threadIdx.x] = v;
    __syncthreads();
    for (int s = NTHR / 2; s > 0; s >>= 1) {
        if (threadIdx.x < s) acc[threadIdx.x] |= acc[threadIdx.x + s];
        __syncthreads();
    }
    if (threadIdx.x == 0) g_ids64 = (acc[0] == 0u) ? 1 : 0;
}

__device__ __forceinline__ unsigned f2key(float f) {
    unsigned u = __float_as_uint(f);
    return u ^ ((u & 0x80000000u) ? 0xFFFFFFFFu : 0x80000000u);
}
__device__ __forceinline__ float key2f(unsigned u) {
    unsigned b = (u & 0x80000000u) ? (u ^ 0x80000000u) : ~u;
    return __uint_as_float(b);
}

struct SmemT {
    union {
        struct {
            unsigned ctr[NBINS];         // 256B: hist -> posBase cursors
            unsigned long long sk[KSEL]; // 2KB: survivors by bin segment
            unsigned cand[2048];         // 8KB: packed threshold-bin cands
        } f;
        unsigned long long all[2048];    // 16KB: exact fallback storage
    } u;
    float2 outVI[KSEL];                  // 2KB
    unsigned s_b, s_rem, cntN, ovf;
};  // ~18.5KB

__global__ __launch_bounds__(NTHR, 6) void topk_kernel(
    const void* __restrict__ ids_raw,
    const float* __restrict__ W,
    float* __restrict__ out_val,
    float* __restrict__ out_idx)
{
    __shared__ SmemT s;
    const int tok  = blockIdx.x;
    const int tid  = threadIdx.x;
    const int lane = tid & 31;
    const int wrp  = tid >> 5;

    if (tid == 0) { s.cntN = 0u; s.s_b = SENT; s.ovf = 0u; }
    if (tid < (int)(NBINS / 16)) ((uint4*)s.u.f.ctr)[tid * 4] = make_uint4(0,0,0,0);
    if (tid < (int)(NBINS / 16)) {
        ((uint4*)s.u.f.ctr)[tid * 4 + 1] = make_uint4(0,0,0,0);
        ((uint4*)s.u.f.ctr)[tid * 4 + 2] = make_uint4(0,0,0,0);
        ((uint4*)s.u.f.ctr)[tid * 4 + 3] = make_uint4(0,0,0,0);
    }

    // ---- gather one embedding row (coalesced float4) ----
    long long id;
    if (g_ids64) id = ((const long long*)ids_raw)[tok];
    else         id = (long long)((const int*)ids_raw)[tok];

    const float4* row = (const float4*)(W + (size_t)id * HID);
    float4 a = __ldg(row + tid);
    float4 b = __ldg(row + tid + NTHR);
    float v[8] = {a.x, a.y, a.z, a.w, b.x, b.y, b.z, b.w};

    __syncthreads();

    // ---- filtered histogram: lazy keys (passers are positive floats) ----
    #pragma unroll
    for (int e = 0; e < 8; e++) {
        if (v[e] >= FTHR) {
            unsigned d = (__float_as_uint(v[e]) ^ 0x80000000u) >> 21;   // >= BASE
            unsigned w2 = d - BASE;
            if (w2 < NBINS) atomicAdd(&s.u.f.ctr[w2], 1u);
            else            s.ovf = 1u;            // benign race
        }
    }
    __syncthreads();

    // ---- suffix scan on warp 0 only (64 bins, 2 per lane) ----
    if (wrp == 0) {
        unsigned b0 = s.u.f.ctr[lane * 2];
        unsigned b1 = s.u.f.ctr[lane * 2 + 1];
        unsigned tsum = b0 + b1;

        unsigned sfx = tsum;                       // sum over lanes >= mine
        #pragma unroll
        for (int off = 1; off < 32; off <<= 1) {
            unsigned y = __shfl_down_sync(FULLW, sfx, off);
            if (lane + off < 32) sfx += y;
        }
        unsigned run = sfx - tsum;                 // counted in bins above mine
        unsigned pb1 = run;
        if (run < KSEL && KSEL <= run + b1) {
            s.s_b = BASE + (unsigned)lane * 2u + 1u;  s.s_rem = KSEL - run;
        }
        run += b1;
        unsigned pb0 = run;
        if (run < KSEL && KSEL <= run + b0) {
            s.s_b = BASE + (unsigned)lane * 2u;       s.s_rem = KSEL - run;
        }
        // Seed scatter cursors with posBase.
        s.u.f.ctr[lane * 2]     = pb0;
        s.u.f.ctr[lane * 2 + 1] = pb1;
    }
    __syncthreads();

    const unsigned bsel = s.s_b;

    if (bsel != SENT && !s.ovf) {
        // ================= FAST PATH (always, in practice) =================
        const unsigned rem = s.s_rem;
        const int      nG  = (int)(KSEL - rem);

        // Scatter: passers only; d >= bsel implies in-window.
        #pragma unroll
        for (int e = 0; e < 8; e++) {
            if (v[e] < FTHR) continue;
            unsigned k = __float_as_uint(v[e]) ^ 0x80000000u;
            unsigned d = k >> 21;
            if (d < bsel) continue;
            int idx = (e < 4) ? (tid * 4 + e) : ((tid + NTHR) * 4 + (e - 4));
            if (d > bsel) {
                unsigned slot = atomicAdd(&s.u.f.ctr[d - BASE], 1u);
                s.u.f.sk[slot] = ((unsigned long long)k << 32) | (unsigned)(~idx);
            } else {
                unsigned slot = atomicAdd(&s.cntN, 1u);
                s.u.f.cand[slot] = ((k & 0x1FFFFFu) << 11) | (0x7FFu ^ (unsigned)idx);
            }
        }
        __syncthreads();

        const int n1 = (int)s.cntN;

        // Survivors: rank within own bin segment [ctr[d+1], ctr[d]).
        if (tid < nG) {
            unsigned long long my = s.u.f.sk[tid];
            const unsigned d = (unsigned)(my >> 53);
            unsigned lo = (d == BASE + NBINS - 1u) ? 0u : s.u.f.ctr[d + 1u - BASE];
            unsigned hi = s.u.f.ctr[d - BASE];
            int rank = 0;
            for (unsigned j = lo; j < hi; j++)
                rank += (s.u.f.sk[j] > my);
            s.outVI[lo + rank] = make_float2(key2f((unsigned)(my >> 32)),
                                             (float)((int)(~(unsigned)my)));
        }

        // Threshold bin: rank-select top `rem` into slots [nG, 256).
        for (int t = tid; t < n1; t += NTHR) {
            unsigned my = s.u.f.cand[t];
            int rank = 0;
            for (int j = 0; j < n1; j++) rank += (s.u.f.cand[j] > my);
            if (rank < (int)rem) {
                unsigned k   = (bsel << 21) | (my >> 11);
                unsigned idx = 0x7FFu ^ (my & 0x7FFu);
                s.outVI[nG + rank] = make_float2(key2f(k), (float)idx);
            }
        }
    } else {
        // ====== EXACT FALLBACK (sentinel or overflow; brute force) ======
        __syncthreads();
        #pragma unroll
        for (int e = 0; e < 8; e++) {
            unsigned k = f2key(v[e]);
            int idx = (e < 4) ? (tid * 4 + e) : ((tid + NTHR) * 4 + (e - 4));
            s.u.all[idx] = ((unsigned long long)k << 32) | (unsigned)(~idx);
        }
        __syncthreads();
        #pragma unroll
        for (int e = 0; e < 8; e++) {
            int idx = (e < 4) ? (tid * 4 + e) : ((tid + NTHR) * 4 + (e - 4));
            unsigned long long my = s.u.all[idx];
            int rank = 0;
            for (int j = 0; j < HID; j++) rank += (s.u.all[j] > my);
            if (rank < KSEL)
                s.outVI[rank] = make_float2(key2f((unsigned)(my >> 32)),
                                            (float)((int)(~(unsigned)my)));
        }
    }
    __syncthreads();

    // ---- single fully-coalesced global write ----
    float2 r = s.outVI[tid];
    out_val[(size_t)tok * KSEL + tid] = r.x;
    out_idx[(size_t)tok * KSEL + tid] = r.y;
}

extern "C" void kernel_launch(void* const* d_in, const int* in_sizes, int n_in,
                              void* d_out, int out_size)
{
    const void*  ids = d_in[0];
    const float* W   = (const float*)d_in[1];

    float* out_val = (float*)d_out;
    float* out_idx = (float*)d_out + (size_t)NTOK * KSEL;

    detect_ids_kernel<<<1, NTHR>>>((const unsigned int*)ids);
    topk_kernel<<<NTOK, NTHR>>>(ids, W, out_val, out_idx);
}

// round 17
// speedup vs baseline: 1.0314x; 1.0314x over previous
#include <cuda_runtime.h>
#include <cuda_bf16.h>
#include <cstdint>

#define HID   2048
#define KSEL  256
#define NTOK  16384
#define NTHR  256
#define FULLW 0xFFFFFFFFu
// Filter: v >= 0.875f  <=>  key >= 0xBF600000  <=>  bin >= 1531 (bin-aligned).
#define FTHR  0.875f
#define BASE  1531u          // first bin of the 64-bin window
#define NBINS 64u            // window [1531, 1595): covers values up to ~57344
#define SENT  0xFFFFFFFFu

__device__ int g_ids64;

// Detect int32 vs int64 ids (odd 32-bit words all zero => int64).
__global__ void detect_ids_kernel(const unsigned int* __restrict__ w) {
    __shared__ unsigned acc[NTHR];
    unsigned v = 0;
    for (int i = threadIdx.x; i < NTOK / 2; i += NTHR) v |= w[2 * i + 1];
    acc[threadIdx.x] = v;
    __syncthreads();
    for (int s = NTHR / 2; s > 0; s >>= 1) {
        if (threadIdx.x < s) acc[threadIdx.x] |= acc[threadIdx.x + s];
        __syncthreads();
    }
    if (threadIdx.x == 0) g_ids64 = (acc[0] == 0u) ? 1 : 0;
}

__device__ __forceinline__ unsigned f2key(float f) {
    unsigned u = __float_as_uint(f);
    return u ^ ((u & 0x80000000u) ? 0xFFFFFFFFu : 0x80000000u);
}
__device__ __forceinline__ float key2f(unsigned u) {
    unsigned b = (u & 0x80000000u) ? (u ^ 0x80000000u) : ~u;
    return __uint_as_float(b);
}

struct SmemT {
    union {
        struct {
            unsigned ctr[NBINS];         // 256B: hist -> posBase cursors
            unsigned long long sk[KSEL]; // 2KB: survivors by bin segment
            unsigned cand[2048];         // 8KB: packed threshold-bin cands
        } f;
        unsigned long long all[2048];    // 16KB: exact fallback storage
    } u;
    float2 outVI[KSEL];                  // 2KB
    unsigned s_b, s_rem, cntN, ovf;
};  // ~18.5KB

__global__ __launch_bounds__(NTHR, 6) void topk_kernel(
    const void* __restrict__ ids_raw,
    const float* __restrict__ W,
    float* __restrict__ out_val,
    float* __restrict__ out_idx)
{
    __shared__ SmemT s;
    const int tok  = blockIdx.x;
    const int tid  = threadIdx.x;
    const int lane = tid & 31;
    const int wrp  = tid >> 5;

    if (tid == 0) { s.cntN = 0u; s.s_b = SENT; s.ovf = 0u; }
    if (tid < (int)(NBINS / 4)) ((uint4*)s.u.f.ctr)[tid] = make_uint4(0,0,0,0);

    // ---- gather one embedding row (coalesced float4) ----
    long long id;
    if (g_ids64) id = ((const long long*)ids_raw)[tok];
    else         id = (long long)((const int*)ids_raw)[tok];

    const float4* row = (const float4*)(W + (size_t)id * HID);
    float4 a = __ldg(row + tid);
    float4 b = __ldg(row + tid + NTHR);
    float v[8] = {a.x, a.y, a.z, a.w, b.x, b.y, b.z, b.w};

    __syncthreads();

    // ---- filtered histogram: lazy keys (passers are positive floats) ----
    #pragma unroll
    for (int e = 0; e < 8; e++) {
        if (v[e] >= FTHR) {
            unsigned d = (__float_as_uint(v[e]) ^ 0x80000000u) >> 21;   // >= BASE
            unsigned w2 = d - BASE;
            if (w2 < NBINS) atomicAdd(&s.u.f.ctr[w2], 1u);
            else            s.ovf = 1u;            // benign race
        }
    }
    __syncthreads();

    // ---- suffix scan on warp 0 only (64 bins, 2 per lane) ----
    if (wrp == 0) {
        unsigned b0 = s.u.f.ctr[lane * 2];
        unsigned b1 = s.u.f.ctr[lane * 2 + 1];
        unsigned tsum = b0 + b1;

        unsigned sfx = tsum;                       // sum over lanes >= mine
        #pragma unroll
        for (int off = 1; off < 32; off <<= 1) {
            unsigned y = __shfl_down_sync(FULLW, sfx, off);
            if (lane + off < 32) sfx += y;
        }
        unsigned run = sfx - tsum;                 // counted in bins above mine
        unsigned pb1 = run;
        if (run < KSEL && KSEL <= run + b1) {
            s.s_b = BASE + (unsigned)lane * 2u + 1u;  s.s_rem = KSEL - run;
        }
        run += b1;
        unsigned pb0 = run;
        if (run < KSEL && KSEL <= run + b0) {
            s.s_b = BASE + (unsigned)lane * 2u;       s.s_rem = KSEL - run;
        }
        // Seed scatter cursors with posBase.
        s.u.f.ctr[lane * 2]     = pb0;
        s.u.f.ctr[lane * 2 + 1] = pb1;
    }
    __syncthreads();

    const unsigned bsel = s.s_b;

    if (bsel != SENT && !s.ovf) {
        // ================= FAST PATH (always, in practice) =================
        const unsigned rem = s.s_rem;
        const int      nG  = (int)(KSEL - rem);

        // Scatter: passers only; d >= bsel implies in-window.
        #pragma unroll
        for (int e = 0; e < 8; e++) {
            if (v[e] < FTHR) continue;
            unsigned k = __float_as_uint(v[e]) ^ 0x80000000u;
            unsigned d = k >> 21;
            if (d < bsel) continue;
            int idx = (e < 4) ? (tid * 4 + e) : ((tid + NTHR) * 4 + (e - 4));
            if (d > bsel) {
                unsigned slot = atomicAdd(&s.u.f.ctr[d - BASE], 1u);
                s.u.f.sk[slot] = ((unsigned long long)k << 32) | (unsigned)(~idx);
            } else {
                unsigned slot = atomicAdd(&s.cntN, 1u);
                s.u.f.cand[slot] = ((k & 0x1FFFFFu) << 11) | (0x7FFu ^ (unsigned)idx);
            }
        }
        __syncthreads();

        const int n1 = (int)s.cntN;

        // ---- rank phases, load-balanced across the whole CTA ----
        // Low threads [0, nG): survivors, rank within own bin segment.
        // High threads (reversed mapping): threshold-bin rank-select.
        // No barrier between them: disjoint reads (sk/ctr vs cand) and
        // disjoint outVI slots ([0,nG) vs [nG,256)).

        if (tid < nG) {
            unsigned long long my = s.u.f.sk[tid];
            const unsigned d = (unsigned)(my >> 53);
            unsigned lo = (d == BASE + NBINS - 1u) ? 0u : s.u.f.ctr[d + 1u - BASE];
            unsigned hi = s.u.f.ctr[d - BASE];
            int rank = 0;
            for (unsigned j = lo; j < hi; j++)
                rank += (s.u.f.sk[j] > my);
            s.outVI[lo + rank] = make_float2(key2f((unsigned)(my >> 32)),
                                             (float)((int)(~(unsigned)my)));
        }

        // Threshold bin: thread (255 - j) handles cand[j] (complementary to
        // the survivor range since nG + n1 >= 256).
        for (int t = (NTHR - 1) - tid; t < n1; t += NTHR) {
            unsigned my = s.u.f.cand[t];
            int rank = 0;
            int j = 0;
            for (; j + 1 < n1; j += 2) {           // one LDS.64 per 2 cands
                uint2 c2 = *(const uint2*)&s.u.f.cand[j];
                rank += (c2.x > my) + (c2.y > my);
            }
            if (j < n1) rank += (s.u.f.cand[j] > my);
            if (rank < (int)rem) {
                unsigned k   = (bsel << 21) | (my >> 11);
                unsigned idx = 0x7FFu ^ (my & 0x7FFu);
                s.outVI[nG + rank] = make_float2(key2f(k), (float)idx);
            }
        }
    } else {
        // ====== EXACT FALLBACK (sentinel or overflow; brute force) ======
        __syncthreads();
        #pragma unroll
        for (int e = 0; e < 8; e++) {
            unsigned k = f2key(v[e]);
            int idx = (e < 4) ? (tid * 4 + e) : ((tid + NTHR) * 4 + (e - 4));
            s.u.all[idx] = ((unsigned long long)k << 32) | (unsigned)(~idx);
        }
        __syncthreads();
        #pragma unroll
        for (int e = 0; e < 8; e++) {
            int idx = (e < 4) ? (tid * 4 + e) : ((tid + NTHR) * 4 + (e - 4));
            unsigned long long my = s.u.all[idx];
            int rank = 0;
            for (int j = 0; j < HID; j++) rank += (s.u.all[j] > my);
            if (rank < KSEL)
                s.outVI[rank] = make_float2(key2f((unsigned)(my >> 32)),
                                            (float)((int)(~(unsigned)my)));
        }
    }
    __syncthreads();

    // ---- single fully-coalesced global write ----
    float2 r = s.outVI[tid];
    out_val[(size_t)tok * KSEL + tid] = r.x;
    out_idx[(size_t)tok * KSEL + tid] = r.y;
}

extern "C" void kernel_launch(void* const* d_in, const int* in_sizes, int n_in,
                              void* d_out, int out_size)
{
    const void*  ids = d_in[0];
    const float* W   = (const float*)d_in[1];

    float* out_val = (float*)d_out;
    float* out_idx = (float*)d_out + (size_t)NTOK * KSEL;

    detect_ids_kernel<<<1, NTHR>>>((const unsigned int*)ids);
    topk_kernel<<<NTOK, NTHR>>>(ids, W, out_val, out_idx);
}